// round 9
// baseline (speedup 1.0000x reference)
#include <cuda_runtime.h>
#include <cuda_fp16.h>
#include <cstdint>
#include <math.h>

// ---------------------------------------------------------------------------
// MixtralMoE: T=16384, H=1024, I=3584, E=8, top-2.
// v9 == v8 resubmitted (R8 bench was an infra failure: container broker died;
// the kernel itself was never executed). BK=64 / NST=3 cp.async pipeline
// (half the syncs), 1-pointer-per-operand chunk mapping, merged cvt kernel.
// Engine: mma.sync.m16n8k16 f16 (f32 acc).
// ---------------------------------------------------------------------------

#define TOKENS 16384
#define HIDDEN 1024
#define INTER  3584
#define NEXP   8
#define SLOTS  (TOKENS * 2)

#define BM 128
#define BK 64                        // K halves per stage
#define SKH 72                       // smem row stride in halves (144 B)
#define STAGE_B (BM * SKH * 2)       // 18432 B per operand per stage
#define NST 3
#define K_SMEM (NST * 2 * STAGE_B)   // 110592 B

#define MAXP   (SLOTS + NEXP * BM)   // 33792
#define MTILES (MAXP / BM)           // 264
#define ESTRIDE ((long)INTER * HIDDEN)

// ------------------------- device scratch ----------------------------------
__device__ __half g_xh[(size_t)TOKENS * HIDDEN];
__device__ __half g_w1h[(size_t)NEXP * ESTRIDE];
__device__ __half g_w3h[(size_t)NEXP * ESTRIDE];
__device__ __half g_w2h[(size_t)NEXP * ESTRIDE];
__device__ __half g_act[(size_t)MAXP * INTER];
__device__ __half g_y[(size_t)MAXP * HIDDEN];
__device__ int    g_perm[MAXP];
__device__ int    g_slot[SLOTS];
__device__ float  g_tkw[SLOTS];
__device__ int    g_tke[SLOTS];
__device__ int    g_cnt[NEXP];
__device__ int    g_cur[NEXP];
__device__ int    g_off[NEXP + 1];

// ------------------------------ helpers -------------------------------------
__device__ __forceinline__ uint32_t smem_u32(const void* p) {
    return (uint32_t)__cvta_generic_to_shared(p);
}

#define CP_ASYNC16(dst_u32, src_ptr, szr) \
    asm volatile("cp.async.cg.shared.global [%0], [%1], 16, %2;" \
        :: "r"(dst_u32), "l"(src_ptr), "r"(szr))
#define CP_COMMIT() asm volatile("cp.async.commit_group;" ::: "memory")
#define CP_WAIT1()  asm volatile("cp.async.wait_group 1;" ::: "memory")

#define LDSM_X4(r0, r1, r2, r3, a) \
    asm volatile("ldmatrix.sync.aligned.m8n8.x4.shared.b16 {%0,%1,%2,%3}, [%4];" \
        : "=r"(r0), "=r"(r1), "=r"(r2), "=r"(r3) : "r"(a))

__device__ __forceinline__ void mma_f16(float* c, const uint32_t* a, const uint32_t* b) {
    asm volatile(
        "mma.sync.aligned.m16n8k16.row.col.f32.f16.f16.f32 "
        "{%0,%1,%2,%3}, {%4,%5,%6,%7}, {%8,%9}, {%0,%1,%2,%3};"
        : "+f"(c[0]), "+f"(c[1]), "+f"(c[2]), "+f"(c[3])
        : "r"(a[0]), "r"(a[1]), "r"(a[2]), "r"(a[3]), "r"(b[0]), "r"(b[1]));
}

__device__ __forceinline__ float silu(float h) { return h / (1.f + expf(-h)); }

// --------------------- merged cvt f32 -> f16 (x, w1, w3, w2) ----------------
#define X4 (TOKENS * HIDDEN / 4)             // 4194304 quads
#define W4 (NEXP * INTER * HIDDEN / 4)       // 7340032 quads
#define CVT_TOT (X4 + 3 * W4)                // 26214400 quads

__global__ void cvt_all_kernel(const float* __restrict__ x,
                               const float* __restrict__ w1,
                               const float* __restrict__ w3,
                               const float* __restrict__ w2) {
    int i = blockIdx.x * blockDim.x + threadIdx.x;
    if (i >= CVT_TOT) return;
    const float* src; __half* dst; size_t off;
    if (i < X4)               { src = x;  dst = g_xh;  off = (size_t)i; }
    else if (i < X4 + W4)     { src = w1; dst = g_w1h; off = (size_t)(i - X4); }
    else if (i < X4 + 2 * W4) { src = w3; dst = g_w3h; off = (size_t)(i - X4 - W4); }
    else                      { src = w2; dst = g_w2h; off = (size_t)(i - X4 - 2 * W4); }
    float4 v = ((const float4*)src)[off];
    __half2 lo = __float22half2_rn(make_float2(v.x, v.y));
    __half2 hi = __float22half2_rn(make_float2(v.z, v.w));
    uint2 p;
    p.x = *(uint32_t*)&lo;
    p.y = *(uint32_t*)&hi;
    ((uint2*)dst)[off] = p;
}

// ------------------------------ init ---------------------------------------
__global__ void init_kernel() {
    int i = blockIdx.x * blockDim.x + threadIdx.x;
    if (i < NEXP) { g_cnt[i] = 0; g_cur[i] = 0; }
    if (i < MAXP) g_perm[i] = -1;
}

// ------------------------------ router -------------------------------------
__global__ void router_kernel(const float* __restrict__ x,
                              const float* __restrict__ gw) {
    __shared__ float sgw[NEXP * HIDDEN];
    int tid = threadIdx.x;
    for (int i = tid; i < NEXP * HIDDEN; i += 256) sgw[i] = gw[i];
    __syncthreads();

    int warp = tid >> 5, lane = tid & 31;
    int t = blockIdx.x * 8 + warp;
    const float* xr = x + (long)t * HIDDEN;

    float lg[NEXP];
#pragma unroll
    for (int e = 0; e < NEXP; e++) {
        float s = 0.f;
        const float* w = sgw + e * HIDDEN;
        for (int h = lane; h < HIDDEN; h += 32) s += xr[h] * w[h];
#pragma unroll
        for (int o = 16; o > 0; o >>= 1) s += __shfl_xor_sync(0xFFFFFFFFu, s, o);
        lg[e] = s;
    }
    if (lane == 0) {
        int i0 = 0;
#pragma unroll
        for (int e = 1; e < NEXP; e++) if (lg[e] > lg[i0]) i0 = e;
        int i1 = -1;
#pragma unroll
        for (int e = 0; e < NEXP; e++) {
            if (e == i0) continue;
            if (i1 < 0 || lg[e] > lg[i1]) i1 = e;
        }
        float w0 = 1.f / (1.f + expf(lg[i1] - lg[i0]));
        g_tke[t * 2 + 0] = i0;  g_tkw[t * 2 + 0] = w0;
        g_tke[t * 2 + 1] = i1;  g_tkw[t * 2 + 1] = 1.f - w0;
        atomicAdd(&g_cnt[i0], 1);
        atomicAdd(&g_cnt[i1], 1);
    }
}

__global__ void offsets_kernel() {
    g_off[0] = 0;
    for (int e = 0; e < NEXP; e++)
        g_off[e + 1] = g_off[e] + ((g_cnt[e] + BM - 1) / BM) * BM;
}

__global__ void scatter_kernel() {
    int i = blockIdx.x * blockDim.x + threadIdx.x;
    if (i >= SLOTS) return;
    int e = g_tke[i];
    int pos = g_off[e] + atomicAdd(&g_cur[e], 1);
    g_perm[pos] = i >> 1;
    g_slot[i] = pos;
}

// ---------------------------------------------------------------------------
// Fragment compute: warp tile 32(m) x 64(n), BK=64 per stage (4 x k16).
// ---------------------------------------------------------------------------
__device__ __forceinline__ void stage_mma(uint32_t a_u32, uint32_t b_u32,
                                          int wm, int wn, int lane,
                                          float c[2][8][4]) {
    const int mat = lane >> 3, r = lane & 7;
#pragma unroll
    for (int kk = 0; kk < 4; kk++) {
        uint32_t af[2][4];
#pragma unroll
        for (int t = 0; t < 2; t++) {
            int row = wm * 32 + t * 16 + ((mat & 1) << 3) + r;
            int kc  = kk * 16 + ((mat >> 1) << 3);
            LDSM_X4(af[t][0], af[t][1], af[t][2], af[t][3],
                    a_u32 + (uint32_t)(row * (SKH * 2) + kc * 2));
        }
        uint32_t bf[8][2];
#pragma unroll
        for (int ug = 0; ug < 4; ug++) {
            int u = ug * 2;
            int n  = wn * 64 + (u + (mat >> 1)) * 8 + r;
            int kc = kk * 16 + ((mat & 1) << 3);
            LDSM_X4(bf[u][0], bf[u][1], bf[u + 1][0], bf[u + 1][1],
                    b_u32 + (uint32_t)(n * (SKH * 2) + kc * 2));
        }
#pragma unroll
        for (int t = 0; t < 2; t++)
#pragma unroll
            for (int u = 0; u < 8; u++)
                mma_f16(c[t][u], af[t], bf[u]);
    }
}

// issue one stage's cp.async: each thread owns half a row (4 x 16B chunks)
__device__ __forceinline__ void issue_stage(uint32_t base, uint32_t adst, uint32_t bdst,
                                            const __half* asrc, const __half* bsrc,
                                            uint32_t asz, int koff) {
#pragma unroll
    for (int q = 0; q < 4; q++)
        CP_ASYNC16(base + adst + q * 16, asrc + koff + q * 8, asz);
#pragma unroll
    for (int q = 0; q < 4; q++)
        CP_ASYNC16(base + STAGE_B + bdst + q * 16, bsrc + koff + q * 8, 16u);
}

// ------------------------- fused up kernel (w1 & w3 + SwiGLU) ---------------
__global__ void __launch_bounds__(256, 2)
up_kernel() {
    int row_base = blockIdx.y * BM;
    if (row_base >= g_off[NEXP]) return;
    int e = 0;
    while (g_off[e + 1] <= row_base) e++;
    const int col_base = blockIdx.x * 64;
    const __half* __restrict__ pw1 = g_w1h + (size_t)e * ESTRIDE;
    const __half* __restrict__ pw3 = g_w3h + (size_t)e * ESTRIDE;

    extern __shared__ __half smem[];
    const uint32_t sb = smem_u32(smem);

    const int tid  = threadIdx.x;
    const int wid  = tid >> 5;
    const int lane = tid & 31;
    const int wm = wid & 3;
    const int wn = wid >> 2;

    // one row-half per thread: r = tid>>1, half-offset h0 = (tid&1)*32 halves
    const int r  = tid >> 1;
    const int h0 = (tid & 1) * 32;
    const uint32_t adst = (uint32_t)(r * 144 + h0 * 2);
    const uint32_t bdst = adst;
    int sr = g_perm[row_base + r];
    const __half* asrc = g_xh + ((sr < 0) ? 0 : (size_t)sr * HIDDEN) + h0;
    const uint32_t asz = (sr < 0) ? 0u : 16u;
    const __half* bsrc = (r < 64) ? (pw1 + (size_t)(col_base + r) * HIDDEN + h0)
                                  : (pw3 + (size_t)(col_base + r - 64) * HIDDEN + h0);

    float c[2][8][4];
#pragma unroll
    for (int t = 0; t < 2; t++)
#pragma unroll
        for (int u = 0; u < 8; u++)
#pragma unroll
            for (int v = 0; v < 4; v++) c[t][u][v] = 0.f;

    const int S = HIDDEN / BK;  // 16
#pragma unroll
    for (int s = 0; s < NST - 1; s++) {
        issue_stage(sb + s * (2 * STAGE_B), adst, bdst, asrc, bsrc, asz, s * BK);
        CP_COMMIT();
    }

#pragma unroll 1
    for (int s = 0; s < S; s++) {
        CP_WAIT1();
        __syncthreads();
        int sn = s + NST - 1;
        if (sn < S)
            issue_stage(sb + (sn % NST) * (2 * STAGE_B), adst, bdst, asrc, bsrc,
                        asz, sn * BK);
        CP_COMMIT();
        uint32_t base = sb + (s % NST) * (2 * STAGE_B);
        stage_mma(base, base + STAGE_B, wm, wn, lane, c);
    }

    // ---- epilogue: exchange u through smem, combine, store fp16 act ----
    __syncthreads();
    float* ux = (float*)smem;   // 128 x 66 f32 = 33792 B <= K_SMEM
    const int gid = lane >> 2, tig = lane & 3;
    if (wn == 1) {
#pragma unroll
        for (int t = 0; t < 2; t++) {
            int r0 = wm * 32 + t * 16 + gid;
#pragma unroll
            for (int u = 0; u < 8; u++) {
                int n = u * 8 + tig * 2;
                ux[r0 * 66 + n]           = c[t][u][0];
                ux[r0 * 66 + n + 1]       = c[t][u][1];
                ux[(r0 + 8) * 66 + n]     = c[t][u][2];
                ux[(r0 + 8) * 66 + n + 1] = c[t][u][3];
            }
        }
    }
    __syncthreads();
    if (wn == 0) {
#pragma unroll
        for (int t = 0; t < 2; t++) {
            int r0 = wm * 32 + t * 16 + gid;
#pragma unroll
            for (int u = 0; u < 8; u++) {
                int n = u * 8 + tig * 2;
                float u00 = ux[r0 * 66 + n],       u01 = ux[r0 * 66 + n + 1];
                float u10 = ux[(r0 + 8) * 66 + n], u11 = ux[(r0 + 8) * 66 + n + 1];
                __half2 h0v = __float22half2_rn(make_float2(silu(c[t][u][0]) * u00,
                                                            silu(c[t][u][1]) * u01));
                __half2 h1v = __float22half2_rn(make_float2(silu(c[t][u][2]) * u10,
                                                            silu(c[t][u][3]) * u11));
                *(__half2*)(g_act + (size_t)(row_base + r0) * INTER + col_base + n) = h0v;
                *(__half2*)(g_act + (size_t)(row_base + r0 + 8) * INTER + col_base + n) = h1v;
            }
        }
    }
}

// ------------------------------ down kernel (w2) ----------------------------
__global__ void __launch_bounds__(256, 2)
down_kernel() {
    int row_base = blockIdx.y * BM;
    if (row_base >= g_off[NEXP]) return;
    int e = 0;
    while (g_off[e + 1] <= row_base) e++;
    const int col_base = blockIdx.x * 128;
    const __half* __restrict__ pw2 = g_w2h + (size_t)e * ESTRIDE;

    extern __shared__ __half smem[];
    const uint32_t sb = smem_u32(smem);

    const int tid  = threadIdx.x;
    const int wid  = tid >> 5;
    const int lane = tid & 31;
    const int wm = wid & 3;
    const int wn = wid >> 2;

    const int r  = tid >> 1;
    const int h0 = (tid & 1) * 32;
    const uint32_t adst = (uint32_t)(r * 144 + h0 * 2);
    const uint32_t bdst = adst;
    const __half* asrc = g_act + (size_t)(row_base + r) * INTER + h0;
    const __half* bsrc = pw2 + (size_t)(col_base + r) * INTER + h0;

    float c[2][8][4];
#pragma unroll
    for (int t = 0; t < 2; t++)
#pragma unroll
        for (int u = 0; u < 8; u++)
#pragma unroll
            for (int v = 0; v < 4; v++) c[t][u][v] = 0.f;

    const int S = INTER / BK;  // 56
#pragma unroll
    for (int s = 0; s < NST - 1; s++) {
        issue_stage(sb + s * (2 * STAGE_B), adst, bdst, asrc, bsrc, 16u, s * BK);
        CP_COMMIT();
    }

#pragma unroll 1
    for (int s = 0; s < S; s++) {
        CP_WAIT1();
        __syncthreads();
        int sn = s + NST - 1;
        if (sn < S)
            issue_stage(sb + (sn % NST) * (2 * STAGE_B), adst, bdst, asrc, bsrc,
                        16u, sn * BK);
        CP_COMMIT();
        uint32_t base = sb + (s % NST) * (2 * STAGE_B);
        stage_mma(base, base + STAGE_B, wm, wn, lane, c);
    }

    const int gid = lane >> 2, tig = lane & 3;
#pragma unroll
    for (int t = 0; t < 2; t++) {
        int m0 = row_base + wm * 32 + t * 16 + gid;
#pragma unroll
        for (int u = 0; u < 8; u++) {
            int n = col_base + wn * 64 + u * 8 + tig * 2;
            __half2 y0 = __float22half2_rn(make_float2(c[t][u][0], c[t][u][1]));
            __half2 y1 = __float22half2_rn(make_float2(c[t][u][2], c[t][u][3]));
            *(__half2*)(g_y + (size_t)m0 * HIDDEN + n)       = y0;
            *(__half2*)(g_y + (size_t)(m0 + 8) * HIDDEN + n) = y1;
        }
    }
}

// ------------------------------ combine ------------------------------------
__global__ void combine_kernel(float* __restrict__ out) {
    int gid = blockIdx.x * blockDim.x + threadIdx.x;
    int t = gid >> 8;
    int c = gid & 255;
    int s0 = g_slot[t * 2 + 0], s1 = g_slot[t * 2 + 1];
    float w0 = g_tkw[t * 2 + 0], w1 = g_tkw[t * 2 + 1];
    uint2 pa = *((const uint2*)(g_y + (size_t)s0 * HIDDEN) + c);
    uint2 pb = *((const uint2*)(g_y + (size_t)s1 * HIDDEN) + c);
    float2 a0 = __half22float2(*(__half2*)&pa.x);
    float2 a1 = __half22float2(*(__half2*)&pa.y);
    float2 b0 = __half22float2(*(__half2*)&pb.x);
    float2 b1 = __half22float2(*(__half2*)&pb.y);
    float4 o;
    o.x = w0 * a0.x + w1 * b0.x;
    o.y = w0 * a0.y + w1 * b0.y;
    o.z = w0 * a1.x + w1 * b1.x;
    o.w = w0 * a1.y + w1 * b1.y;
    ((float4*)out)[gid] = o;
}

// ------------------------------ launcher -----------------------------------
extern "C" void kernel_launch(void* const* d_in, const int* in_sizes, int n_in,
                              void* d_out, int out_size) {
    const float* x  = (const float*)d_in[0];
    const float* gw = (const float*)d_in[1];
    const float* w1 = (const float*)d_in[2];
    const float* w3 = (const float*)d_in[3];
    const float* w2 = (const float*)d_in[4];
    float* out = (float*)d_out;

    cudaFuncSetAttribute(up_kernel,   cudaFuncAttributeMaxDynamicSharedMemorySize, K_SMEM);
    cudaFuncSetAttribute(down_kernel, cudaFuncAttributeMaxDynamicSharedMemorySize, K_SMEM);

    init_kernel<<<(MAXP + 255) / 256, 256>>>();
    router_kernel<<<TOKENS / 8, 256>>>(x, gw);
    cvt_all_kernel<<<(CVT_TOT + 255) / 256, 256>>>(x, w1, w3, w2);
    offsets_kernel<<<1, 1>>>();
    scatter_kernel<<<(SLOTS + 255) / 256, 256>>>();

    dim3 gUp(INTER / 64, MTILES);     // 56 x 264
    dim3 gDn(HIDDEN / 128, MTILES);   // 8  x 264
    up_kernel<<<gUp, 256, K_SMEM>>>();
    down_kernel<<<gDn, 256, K_SMEM>>>();

    combine_kernel<<<(TOKENS * HIDDEN / 4) / 256, 256>>>(out);
}